// round 10
// baseline (speedup 1.0000x reference)
#include <cuda_runtime.h>
#include <cstdint>

// PeakAligner: L=220, window=[57,87); start=index_max-57 in [0,29]
//   in_bounds <=> start<=28; ss=min(start,28)
//   valid <=> p[57]==max(p[0..191]) && max(p[0..56]) < that max && in_bounds,  p=row+ss
//   out[row][i] = valid ? p[3i] : 0 (i=0..63); mask[row] = !valid
//
// Two-pass register-resident design (fetch only [ss, ss+192) of each row)
// with a distance-2 software pipeline over 4-row batches: compute(b) consumes
// loads issued a full iteration earlier.

#define L_DIM 220
#define WIN_LEN 30
#define WIN_LO 57
#define MAX_START 28
#define RPW 4                     // rows per batch (per warp)
#define NBATCH 8                  // batches per warp (must be even)
#define WARPS_PER_BLOCK 4
#define THREADS 128
#define ROWS_PER_WARP_TOTAL (RPW * NBATCH)   // 32

__device__ __forceinline__ unsigned ford(float f) {
    unsigned u = __float_as_uint(f);
    return u ^ (unsigned)(((int)u >> 31) | 0x80000000);
}
__device__ __forceinline__ float unford(unsigned t) {
    unsigned u = (t & 0x80000000u) ? (t ^ 0x80000000u) : ~t;
    return __uint_as_float(u);
}

__device__ __forceinline__ void pass1_issue(const float* __restrict__ rp, int nrows,
                                            int lane, unsigned wu[RPW]) {
    #pragma unroll
    for (int j = 0; j < RPW; j++) {
        wu[j] = 0u;
        if (j < nrows && lane < WIN_LEN)
            wu[j] = ford(__ldg(rp + j * L_DIM + WIN_LO + lane));
    }
}

__device__ __forceinline__ void pass1_reduce(const unsigned wu[RPW],
                                             int ss[RPW], bool inb[RPW]) {
    #pragma unroll
    for (int j = 0; j < RPW; j++) {
        const unsigned wmax = __reduce_max_sync(0xffffffffu, wu[j]);
        const unsigned wb   = __ballot_sync(0xffffffffu, wu[j] == wmax);
        const int start = __ffs(wb) - 1;
        inb[j] = (start <= MAX_START);
        ss[j]  = min(start, MAX_START);
    }
}

__device__ __forceinline__ void pass2_issue(const float* __restrict__ rp, const int ss[RPW],
                                            int nrows, int lane, float x[RPW][6]) {
    #pragma unroll
    for (int j = 0; j < RPW; j++) {
        const float* p = rp + j * L_DIM + ss[j] + lane;
        #pragma unroll
        for (int k = 0; k < 6; k++)
            x[j][k] = (j < nrows) ? __ldg(p + 32 * k) : 0.0f;
    }
}

__device__ __forceinline__ void compute_store(const float x[RPW][6], const bool inb[RPW],
                                              long long row0, int nrows, int lane,
                                              float* __restrict__ out,
                                              float* __restrict__ mask_out) {
    const int i0 = 3 * lane;
    const int sl = i0 & 31;       // source lane for both outputs (96 % 32 == 0)
    const int jr = i0 >> 5;       // source register index 0..2
    #pragma unroll
    for (int j = 0; j < RPW; j++) {
        if (j >= nrows) break;
        const float Ml = fmaxf(fmaxf(fmaxf(x[j][0], x[j][1]), fmaxf(x[j][2], x[j][3])),
                               fmaxf(x[j][4], x[j][5]));
        const float Pl = (lane < 25) ? fmaxf(x[j][0], x[j][1]) : x[j][0];
        const float M  = unford(__reduce_max_sync(0xffffffffu, ford(Ml)));
        const float P  = unford(__reduce_max_sync(0xffffffffu, ford(Pl)));
        const float v57 = __shfl_sync(0xffffffffu, x[j][1], 25);   // p[57]
        const bool valid = (v57 == M) && (P < M) && inb[j];

        const float a0 = __shfl_sync(0xffffffffu, x[j][0], sl);
        const float a1 = __shfl_sync(0xffffffffu, x[j][1], sl);
        const float a2 = __shfl_sync(0xffffffffu, x[j][2], sl);
        const float b0 = __shfl_sync(0xffffffffu, x[j][3], sl);
        const float b1 = __shfl_sync(0xffffffffu, x[j][4], sl);
        const float b2 = __shfl_sync(0xffffffffu, x[j][5], sl);
        float o0 = (jr == 0) ? a0 : (jr == 1) ? a1 : a2;
        float o1 = (jr == 0) ? b0 : (jr == 1) ? b1 : b2;
        o0 = valid ? o0 : 0.0f;
        o1 = valid ? o1 : 0.0f;

        float* orow = out + (size_t)(row0 + j) * 64;
        __stcs(orow + lane,      o0);
        __stcs(orow + lane + 32, o1);
        if (lane == 0)
            __stcs(mask_out + row0 + j, valid ? 0.0f : 1.0f);
    }
}

__global__ __launch_bounds__(THREADS)
void peak_aligner_kernel(const float* __restrict__ in,
                         float* __restrict__ out,
                         float* __restrict__ mask_out,
                         int K) {
    const int w    = threadIdx.x >> 5;
    const int lane = threadIdx.x & 31;
    const long long warp_id = (long long)blockIdx.x * WARPS_PER_BLOCK + w;
    const long long rbase = warp_id * ROWS_PER_WARP_TOTAL;
    if (rbase >= K) return;

    const float* rp0 = in + rbase * L_DIM;

    // rows available for batch b (0..RPW)
    #define NROWS_OF(b) ((int)max(0LL, min((long long)RPW, (long long)K - (rbase + (long long)(b) * RPW))))

    int ssA[RPW], ssB[RPW];
    bool inbA[RPW], inbB[RPW];
    float xA[RPW][6], xB[RPW][6];
    unsigned wu[RPW];

    // ---- prologue: prime batches 0 (A) and 1 (B) ----
    const int n0 = NROWS_OF(0);
    pass1_issue(rp0, n0, lane, wu);
    pass1_reduce(wu, ssA, inbA);
    pass2_issue(rp0, ssA, n0, lane, xA);

    const int n1 = NROWS_OF(1);
    if (n1 > 0) {
        pass1_issue(rp0 + RPW * L_DIM, n1, lane, wu);
        pass1_reduce(wu, ssB, inbB);
        pass2_issue(rp0 + (size_t)RPW * L_DIM, ssB, n1, lane, xB);
    }

    #pragma unroll 1
    for (int b = 0; b < NBATCH; b += 2) {
        // ---- batch b (A): pass2(b) was issued one full iteration ago ----
        {
            const int nn = (b + 2 < NBATCH) ? NROWS_OF(b + 2) : 0;
            const float* rpn = rp0 + (size_t)(b + 2) * RPW * L_DIM;
            if (nn > 0) pass1_issue(rpn, nn, lane, wu);
            compute_store(xA, inbA, rbase + (long long)b * RPW, NROWS_OF(b),
                          lane, out, mask_out);
            if (nn > 0) {
                pass1_reduce(wu, ssA, inbA);
                pass2_issue(rpn, ssA, nn, lane, xA);
            }
        }
        // ---- batch b+1 (B) ----
        {
            const int nb1 = NROWS_OF(b + 1);
            if (nb1 > 0) {
                const int nn = (b + 3 < NBATCH) ? NROWS_OF(b + 3) : 0;
                const float* rpn = rp0 + (size_t)(b + 3) * RPW * L_DIM;
                if (nn > 0) pass1_issue(rpn, nn, lane, wu);
                compute_store(xB, inbB, rbase + (long long)(b + 1) * RPW, nb1,
                              lane, out, mask_out);
                if (nn > 0) {
                    pass1_reduce(wu, ssB, inbB);
                    pass2_issue(rpn, ssB, nn, lane, xB);
                }
            }
        }
    }
    #undef NROWS_OF
}

extern "C" void kernel_launch(void* const* d_in, const int* in_sizes, int n_in,
                              void* d_out, int out_size) {
    const float* in = (const float*)d_in[0];
    const int K = in_sizes[0] / L_DIM;
    float* out  = (float*)d_out;
    float* mask = out + (size_t)K * 64;
    const long long rows_per_block = (long long)WARPS_PER_BLOCK * ROWS_PER_WARP_TOTAL; // 128
    const int blocks = (int)((K + rows_per_block - 1) / rows_per_block);
    peak_aligner_kernel<<<blocks, THREADS>>>(in, out, mask, K);
}